// round 11
// baseline (speedup 1.0000x reference)
#include <cuda_runtime.h>
#include <cstdint>

// s1, blur: [4, 10, 256, 256] fp32 -> out: [4, 256, 256] fp32.
//
// Per pixel: candidate i (0..10): x_j = s_j + b_j (j<i) else s_j - b_j.
// argmin_i std(x, ddof=1); output mean of winner = sum_i / n.
// Scan identity: sumsq_i = const + 4 * prefixSum(s_j*b_j), so
//   argmin variance == argmin( 4*P_i - sum_i^2 / n ),
//   P_i = prefix sum s_j*b_j ; sum_i = (S-B) + 2 * prefix sum b_j.
//
// FINAL (= round-8 configuration, the measured optimum over 10 designs):
//   - float2 loads with the L2::256B fetch-granule hint: a warp spans
//     exactly 256B per plane, matching the granule (best timed 6.624us,
//     best cold 7.23us / 2.90 TB/s).
//   - plain (default-policy) output stores: .cs streaming stores measured
//     WORSE on the warm graph-replay loop (r10: +0.29us).
//   - 1024 CTAs x 128 threads: smooth per-SM balance, ~36% occupancy.
// Timed results are pinned at the ~6.6us platform floor (launch + DRAM
// ramp); all remaining variance between correct designs is above-floor
// warm-kernel cost, which this configuration minimizes.

#define NPLANES 10
#define HW2     32768    // (256*256)/2 pairs per plane

__device__ __forceinline__ float2 ldg_nc_256(const float2* p) {
    float2 r;
    asm volatile("ld.global.nc.L2::256B.v2.f32 {%0, %1}, [%2];"
                 : "=f"(r.x), "=f"(r.y) : "l"(p));
    return r;
}

__global__ __launch_bounds__(128, 8)
void distregression_kernel(const float2* __restrict__ s1,
                           const float2* __restrict__ blur,
                           float2* __restrict__ out,
                           int npairs)
{
    int t = blockIdx.x * blockDim.x + threadIdx.x;
    if (t >= npairs) return;

    int b   = t >> 15;            // pair / HW2 -> batch
    int hw2 = t & (HW2 - 1);

    const float2* s1p = s1   + (size_t)b * NPLANES * HW2 + hw2;
    const float2* blp = blur + (size_t)b * NPLANES * HW2 + hw2;

    // Front-batch all 20 vector loads (MLP=20, 256B L2 fetch granule).
    float sv[NPLANES][2], bv[NPLANES][2];
    #pragma unroll
    for (int j = 0; j < NPLANES; j++) {
        float2 s = ldg_nc_256(s1p + j * HW2);
        float2 v = ldg_nc_256(blp + j * HW2);
        sv[j][0] = s.x; sv[j][1] = s.y;
        bv[j][0] = v.x; bv[j][1] = v.y;
    }

    const float inv_n = 1.0f / NPLANES;
    float res[2];
    #pragma unroll
    for (int k = 0; k < 2; k++) {
        float S = 0.f, B = 0.f;
        #pragma unroll
        for (int j = 0; j < NPLANES; j++) {
            S += sv[j][k];
            B += bv[j][k];
        }

        float sum = S - B;      // candidate 0: all lo
        float P   = 0.f;        // prefix sum of s_j*b_j
        float bestM = 3.0e38f, bestSum = sum;

        #pragma unroll
        for (int i = 0; i <= NPLANES; i++) {
            float M = fmaf(-sum * inv_n, sum, 4.0f * P);
            if (M < bestM) { bestM = M; bestSum = sum; }   // first index wins ties
            if (i < NPLANES) {
                sum = fmaf(2.0f, bv[i][k], sum);
                P   = fmaf(sv[i][k], bv[i][k], P);
            }
        }
        res[k] = bestSum * inv_n;
    }

    out[t] = make_float2(res[0], res[1]);
}

extern "C" void kernel_launch(void* const* d_in, const int* in_sizes, int n_in,
                              void* d_out, int out_size)
{
    const float2* s1   = (const float2*)d_in[0];
    const float2* blur = (const float2*)d_in[1];
    float2* out = (float2*)d_out;

    int npairs  = out_size / 2;                      // 131072
    int threads = 128;
    int blocks  = (npairs + threads - 1) / threads;  // 1024
    distregression_kernel<<<blocks, threads>>>(s1, blur, out, npairs);
}

// round 12
// speedup vs baseline: 1.0435x; 1.0435x over previous
#include <cuda_runtime.h>
#include <cstdint>

// s1, blur: [4, 10, 256, 256] fp32 -> out: [4, 256, 256] fp32.
//
// Per pixel: candidate i (0..10): x_j = s_j + b_j (j<i) else s_j - b_j.
// argmin_i std(x, ddof=1); output mean of winner = sum_i / n.
// Scan identity: sumsq_i = const + 4 * prefixSum(s_j*b_j), so
//   argmin variance == argmin( 4*P_i - sum_i^2 / n ),
//   P_i = prefix sum s_j*b_j ; sum_i = (S-B) + 2 * prefix sum b_j.
//
// Measured landscape (11 rounds): all correct LDG designs sit on a
// 6.6-6.9us plateau (run noise +/-0.3us; r8 and r11 were bit-identical and
// read 6.624 / 6.912). The kernel is DRAM-wall-bound at ~2.8-3.3 TB/s on
// every load path. Best cold profile: float2 + L2::256B (warp span 256B ==
// fetch granule). This round samples the last untested plateau cell:
// that config at 256 threads/block (512 CTAs, 3-4 CTAs/SM).

#define NPLANES 10
#define HW2     32768    // (256*256)/2 pairs per plane

__device__ __forceinline__ float2 ldg_nc_256(const float2* p) {
    float2 r;
    asm volatile("ld.global.nc.L2::256B.v2.f32 {%0, %1}, [%2];"
                 : "=f"(r.x), "=f"(r.y) : "l"(p));
    return r;
}

__global__ __launch_bounds__(256, 4)
void distregression_kernel(const float2* __restrict__ s1,
                           const float2* __restrict__ blur,
                           float2* __restrict__ out,
                           int npairs)
{
    int t = blockIdx.x * blockDim.x + threadIdx.x;
    if (t >= npairs) return;

    int b   = t >> 15;            // pair / HW2 -> batch
    int hw2 = t & (HW2 - 1);

    const float2* s1p = s1   + (size_t)b * NPLANES * HW2 + hw2;
    const float2* blp = blur + (size_t)b * NPLANES * HW2 + hw2;

    // Front-batch all 20 vector loads (MLP=20, 256B L2 fetch granule).
    float sv[NPLANES][2], bv[NPLANES][2];
    #pragma unroll
    for (int j = 0; j < NPLANES; j++) {
        float2 s = ldg_nc_256(s1p + j * HW2);
        float2 v = ldg_nc_256(blp + j * HW2);
        sv[j][0] = s.x; sv[j][1] = s.y;
        bv[j][0] = v.x; bv[j][1] = v.y;
    }

    const float inv_n = 1.0f / NPLANES;
    float res[2];
    #pragma unroll
    for (int k = 0; k < 2; k++) {
        float S = 0.f, B = 0.f;
        #pragma unroll
        for (int j = 0; j < NPLANES; j++) {
            S += sv[j][k];
            B += bv[j][k];
        }

        float sum = S - B;      // candidate 0: all lo
        float P   = 0.f;        // prefix sum of s_j*b_j
        float bestM = 3.0e38f, bestSum = sum;

        #pragma unroll
        for (int i = 0; i <= NPLANES; i++) {
            float M = fmaf(-sum * inv_n, sum, 4.0f * P);
            if (M < bestM) { bestM = M; bestSum = sum; }   // first index wins ties
            if (i < NPLANES) {
                sum = fmaf(2.0f, bv[i][k], sum);
                P   = fmaf(sv[i][k], bv[i][k], P);
            }
        }
        res[k] = bestSum * inv_n;
    }

    out[t] = make_float2(res[0], res[1]);
}

extern "C" void kernel_launch(void* const* d_in, const int* in_sizes, int n_in,
                              void* d_out, int out_size)
{
    const float2* s1   = (const float2*)d_in[0];
    const float2* blur = (const float2*)d_in[1];
    float2* out = (float2*)d_out;

    int npairs  = out_size / 2;                      // 131072
    int threads = 256;
    int blocks  = (npairs + threads - 1) / threads;  // 512
    distregression_kernel<<<blocks, threads>>>(s1, blur, out, npairs);
}